// round 16
// baseline (speedup 1.0000x reference)
#include <cuda_runtime.h>
#include <cuda_bf16.h>
#include <math.h>
#include <cstdint>

// Problem constants
#define BSZ 2
#define LEN 2048
#define DIM 1024
#define NH  16
#define DH  64
#define D3  3072   // 3*DIM

// ---------------------------------------------------------------------------
// Scratch (static device arrays — no allocation allowed)
// ---------------------------------------------------------------------------
__device__ float g_qkv[(size_t)BSZ * LEN * D3];            // [B*L, 3D] fp32
__device__ float g_ctx[(size_t)BSZ * LEN * DIM];           // [B*L, D] fp32
__device__ float g_psum[(size_t)BSZ * NH * LEN * 16];      // partial row sums
__device__ float g_inv[(size_t)BSZ * NH * LEN];            // 1/rowsum

// bf16 split operands for projection GEMMs (reused for Q planes mid-pipeline)
__device__ __nv_bfloat16 g_ah[(size_t)BSZ * LEN * DIM];    // A hi [M][K]
__device__ __nv_bfloat16 g_al[(size_t)BSZ * LEN * DIM];    // A lo
__device__ __nv_bfloat16 g_bh[(size_t)D3 * DIM];           // B^T hi [N][K]
__device__ __nv_bfloat16 g_bl[(size_t)D3 * DIM];           // B^T lo

// K planes [b][l][DIM]
__device__ __nv_bfloat16 g_kh[(size_t)BSZ * LEN * DIM];
__device__ __nv_bfloat16 g_kl[(size_t)BSZ * LEN * DIM];

// E = exp(logits) planes, [bh][q][k] bf16 hi/lo
__device__ __nv_bfloat16 g_eh[(size_t)BSZ * NH * LEN * LEN];
__device__ __nv_bfloat16 g_el[(size_t)BSZ * NH * LEN * LEN];

// V transposed planes [bh][d][k]
__device__ __nv_bfloat16 g_vth[(size_t)BSZ * NH * DH * LEN];
__device__ __nv_bfloat16 g_vtl[(size_t)BSZ * NH * DH * LEN];

// ---------------------------------------------------------------------------
// mma.sync helper (family-portable PTX — works on compute_103)
// ---------------------------------------------------------------------------
#define MMA_BF16(d, a, b)                                                      \
    asm volatile(                                                              \
        "mma.sync.aligned.m16n8k16.row.col.f32.bf16.bf16.f32 "                \
        "{%0,%1,%2,%3}, {%4,%5,%6,%7}, {%8,%9}, {%0,%1,%2,%3};"               \
        : "+f"((d)[0]), "+f"((d)[1]), "+f"((d)[2]), "+f"((d)[3])              \
        : "r"((a)[0]), "r"((a)[1]), "r"((a)[2]), "r"((a)[3]),                 \
          "r"((b)[0]), "r"((b)[1]))

// ---------------------------------------------------------------------------
// split fp32 -> (hi, lo) bf16, same layout.
// ---------------------------------------------------------------------------
__global__ __launch_bounds__(256) void split_rm_kernel(
    const float* __restrict__ x, __nv_bfloat16* __restrict__ hi,
    __nv_bfloat16* __restrict__ lo, int n)
{
    int i = blockIdx.x * 256 + threadIdx.x;
    if (i < n) {
        float v = x[i];
        __nv_bfloat16 h = __float2bfloat16(v);
        hi[i] = h;
        lo[i] = __float2bfloat16(v - __bfloat162float(h));
    }
}

// ---------------------------------------------------------------------------
// split + transpose: w [K][N] -> hiT/loT [N][K]
// ---------------------------------------------------------------------------
__global__ void split_tr_kernel(const float* __restrict__ w,
                                __nv_bfloat16* __restrict__ hiT,
                                __nv_bfloat16* __restrict__ loT,
                                int K, int N)
{
    __shared__ float t[32][33];
    int x = blockIdx.x * 32 + threadIdx.x;  // n
    int y = blockIdx.y * 32 + threadIdx.y;  // k
#pragma unroll
    for (int i = 0; i < 32; i += 8)
        t[threadIdx.y + i][threadIdx.x] = w[(size_t)(y + i) * N + x];
    __syncthreads();
    int n = blockIdx.x * 32 + threadIdx.y;
    int k = blockIdx.y * 32 + threadIdx.x;
#pragma unroll
    for (int i = 0; i < 32; i += 8) {
        float v = t[threadIdx.x][threadIdx.y + i];
        __nv_bfloat16 h = __float2bfloat16(v);
        size_t o = (size_t)(n + i) * K + k;
        hiT[o] = h;
        loT[o] = __float2bfloat16(v - __bfloat162float(h));
    }
}

// ---------------------------------------------------------------------------
// Split Q,K columns of qkv into per-plane bf16 arrays ([b][l][DIM] layout).
// ---------------------------------------------------------------------------
__global__ __launch_bounds__(256) void qksplit_kernel(
    const float* __restrict__ qkv,
    __nv_bfloat16* __restrict__ qh, __nv_bfloat16* __restrict__ ql,
    __nv_bfloat16* __restrict__ kh, __nv_bfloat16* __restrict__ kl)
{
    size_t i = (size_t)blockIdx.x * 256 + threadIdx.x;   // over BSZ*LEN*2048
    int r = (int)(i >> 11);
    int c = (int)(i & 2047);
    float v = qkv[(size_t)r * D3 + c];
    __nv_bfloat16 h = __float2bfloat16(v);
    __nv_bfloat16 l = __float2bfloat16(v - __bfloat162float(h));
    size_t o = (size_t)r * DIM + (c & 1023);
    if (c < 1024) { qh[o] = h; ql[o] = l; }
    else          { kh[o] = h; kl[o] = l; }
}

// ---------------------------------------------------------------------------
// V transpose + split: Vt[bh][d][l] = split(qkv[b][l][2D + h*64 + d])
// ---------------------------------------------------------------------------
__global__ void vtsplit_kernel(const float* __restrict__ qkv,
                               __nv_bfloat16* __restrict__ vh,
                               __nv_bfloat16* __restrict__ vl)
{
    __shared__ float t[32][33];
    int bh = blockIdx.z, b = bh >> 4, h = bh & 15;
    int l0 = blockIdx.x * 32, d0 = blockIdx.y * 32;
    int tx = threadIdx.x, ty = threadIdx.y;
#pragma unroll
    for (int i = 0; i < 32; i += 8)
        t[ty + i][tx] = qkv[(size_t)(b * LEN + l0 + ty + i) * D3 + 2 * DIM + h * DH + d0 + tx];
    __syncthreads();
#pragma unroll
    for (int i = 0; i < 32; i += 8) {
        float v = t[tx][ty + i];
        __nv_bfloat16 hh = __float2bfloat16(v);
        size_t o = (size_t)(bh * DH + d0 + ty + i) * LEN + l0 + tx;
        vh[o] = hh;
        vl[o] = __float2bfloat16(v - __bfloat162float(hh));
    }
}

// ---------------------------------------------------------------------------
// bf16-split projection GEMM (unchanged from R15 passing version)
// ---------------------------------------------------------------------------
__global__ __launch_bounds__(256) void mma_gemm_kernel(
    const __nv_bfloat16* __restrict__ Ah, const __nv_bfloat16* __restrict__ Al,
    const __nv_bfloat16* __restrict__ Bh, const __nv_bfloat16* __restrict__ Bl,
    float* __restrict__ C, int ldc, int Kd)
{
    __shared__ __nv_bfloat16 sAh[128][40];
    __shared__ __nv_bfloat16 sAl[128][40];
    __shared__ __nv_bfloat16 sBh[128][40];
    __shared__ __nv_bfloat16 sBl[128][40];

    int tid = threadIdx.x;
    int wid = tid >> 5, lid = tid & 31;
    int wm = wid & 3, wn = wid >> 2;
    int g = lid >> 2, t4 = lid & 3;
    int row0 = blockIdx.y * 128, col0 = blockIdx.x * 128;

    float acc[2][8][4];
#pragma unroll
    for (int mt = 0; mt < 2; mt++)
#pragma unroll
        for (int nt = 0; nt < 8; nt++)
#pragma unroll
            for (int i = 0; i < 4; i++) acc[mt][nt][i] = 0.0f;

    for (int kt = 0; kt < Kd; kt += 32) {
#pragma unroll
        for (int e = tid; e < 512; e += 256) {
            int row = e >> 2, cg = (e & 3) * 8;
            size_t ga = (size_t)(row0 + row) * Kd + kt + cg;
            size_t gb = (size_t)(col0 + row) * Kd + kt + cg;
            *(uint4*)&sAh[row][cg] = *(const uint4*)(Ah + ga);
            *(uint4*)&sAl[row][cg] = *(const uint4*)(Al + ga);
            *(uint4*)&sBh[row][cg] = *(const uint4*)(Bh + gb);
            *(uint4*)&sBl[row][cg] = *(const uint4*)(Bl + gb);
        }
        __syncthreads();

#pragma unroll
        for (int ks = 0; ks < 2; ks++) {
            int kc = ks * 16 + t4 * 2;
            uint32_t ah[2][4], al[2][4], bh[8][2], bl[8][2];
#pragma unroll
            for (int mt = 0; mt < 2; mt++) {
                int r = wm * 32 + mt * 16 + g;
                ah[mt][0] = *(const uint32_t*)&sAh[r][kc];
                ah[mt][1] = *(const uint32_t*)&sAh[r + 8][kc];
                ah[mt][2] = *(const uint32_t*)&sAh[r][kc + 8];
                ah[mt][3] = *(const uint32_t*)&sAh[r + 8][kc + 8];
                al[mt][0] = *(const uint32_t*)&sAl[r][kc];
                al[mt][1] = *(const uint32_t*)&sAl[r + 8][kc];
                al[mt][2] = *(const uint32_t*)&sAl[r][kc + 8];
                al[mt][3] = *(const uint32_t*)&sAl[r + 8][kc + 8];
            }
#pragma unroll
            for (int nt = 0; nt < 8; nt++) {
                int r = wn * 64 + nt * 8 + g;
                bh[nt][0] = *(const uint32_t*)&sBh[r][kc];
                bh[nt][1] = *(const uint32_t*)&sBh[r][kc + 8];
                bl[nt][0] = *(const uint32_t*)&sBl[r][kc];
                bl[nt][1] = *(const uint32_t*)&sBl[r][kc + 8];
            }
#pragma unroll
            for (int mt = 0; mt < 2; mt++)
#pragma unroll
                for (int nt = 0; nt < 8; nt++) {
                    MMA_BF16(acc[mt][nt], ah[mt], bh[nt]);
                    MMA_BF16(acc[mt][nt], ah[mt], bl[nt]);
                    MMA_BF16(acc[mt][nt], al[mt], bh[nt]);
                }
        }
        __syncthreads();
    }

#pragma unroll
    for (int mt = 0; mt < 2; mt++) {
        int r = row0 + wm * 32 + mt * 16 + g;
#pragma unroll
        for (int nt = 0; nt < 8; nt++) {
            int c = col0 + wn * 64 + nt * 8 + t4 * 2;
            *(float2*)(C + (size_t)r * ldc + c)       = make_float2(acc[mt][nt][0], acc[mt][nt][1]);
            *(float2*)(C + (size_t)(r + 8) * ldc + c) = make_float2(acc[mt][nt][2], acc[mt][nt][3]);
        }
    }
}

// ---------------------------------------------------------------------------
// QK^T on mma.sync with fused exp epilogue.
// Per (b,h): S[q,kseq] = sum_dh Q[q][dh]*K[kseq][dh]; e = exp(0.125*S + bias).
// Writes E as bf16 hi/lo planes + partial row sums.
// ---------------------------------------------------------------------------
__global__ __launch_bounds__(256) void qk_mma_kernel(
    const __nv_bfloat16* __restrict__ Qh_, const __nv_bfloat16* __restrict__ Ql_,
    const __nv_bfloat16* __restrict__ Kh_, const __nv_bfloat16* __restrict__ Kl_,
    const float* __restrict__ bias,
    __nv_bfloat16* __restrict__ Eh, __nv_bfloat16* __restrict__ El,
    float* __restrict__ psum)
{
    __shared__ __nv_bfloat16 sQh[128][40];
    __shared__ __nv_bfloat16 sQl[128][40];
    __shared__ __nv_bfloat16 sKh[128][40];
    __shared__ __nv_bfloat16 sKl[128][40];
    __shared__ float sred[128][9];

    int tid = threadIdx.x;
    int wid = tid >> 5, lid = tid & 31;
    int wm = wid & 3, wn = wid >> 2;
    int g = lid >> 2, t4 = lid & 3;
    int bh = blockIdx.z, b = bh >> 4, h = bh & 15;
    int row0 = blockIdx.y * 128, col0 = blockIdx.x * 128;

    const __nv_bfloat16* Qh = Qh_ + (size_t)b * LEN * DIM + h * DH;
    const __nv_bfloat16* Ql = Ql_ + (size_t)b * LEN * DIM + h * DH;
    const __nv_bfloat16* Kh = Kh_ + (size_t)b * LEN * DIM + h * DH;
    const __nv_bfloat16* Kl = Kl_ + (size_t)b * LEN * DIM + h * DH;

    float acc[2][8][4];
#pragma unroll
    for (int mt = 0; mt < 2; mt++)
#pragma unroll
        for (int nt = 0; nt < 8; nt++)
#pragma unroll
            for (int i = 0; i < 4; i++) acc[mt][nt][i] = 0.0f;

    for (int kt = 0; kt < DH; kt += 32) {
#pragma unroll
        for (int e = tid; e < 512; e += 256) {
            int row = e >> 2, cg = (e & 3) * 8;
            size_t gq = (size_t)(row0 + row) * DIM + kt + cg;
            size_t gk = (size_t)(col0 + row) * DIM + kt + cg;
            *(uint4*)&sQh[row][cg] = *(const uint4*)(Qh + gq);
            *(uint4*)&sQl[row][cg] = *(const uint4*)(Ql + gq);
            *(uint4*)&sKh[row][cg] = *(const uint4*)(Kh + gk);
            *(uint4*)&sKl[row][cg] = *(const uint4*)(Kl + gk);
        }
        __syncthreads();

#pragma unroll
        for (int ks = 0; ks < 2; ks++) {
            int kc = ks * 16 + t4 * 2;
            uint32_t ah[2][4], al[2][4], bhf[8][2], blf[8][2];
#pragma unroll
            for (int mt = 0; mt < 2; mt++) {
                int r = wm * 32 + mt * 16 + g;
                ah[mt][0] = *(const uint32_t*)&sQh[r][kc];
                ah[mt][1] = *(const uint32_t*)&sQh[r + 8][kc];
                ah[mt][2] = *(const uint32_t*)&sQh[r][kc + 8];
                ah[mt][3] = *(const uint32_t*)&sQh[r + 8][kc + 8];
                al[mt][0] = *(const uint32_t*)&sQl[r][kc];
                al[mt][1] = *(const uint32_t*)&sQl[r + 8][kc];
                al[mt][2] = *(const uint32_t*)&sQl[r][kc + 8];
                al[mt][3] = *(const uint32_t*)&sQl[r + 8][kc + 8];
            }
#pragma unroll
            for (int nt = 0; nt < 8; nt++) {
                int r = wn * 64 + nt * 8 + g;
                bhf[nt][0] = *(const uint32_t*)&sKh[r][kc];
                bhf[nt][1] = *(const uint32_t*)&sKh[r][kc + 8];
                blf[nt][0] = *(const uint32_t*)&sKl[r][kc];
                blf[nt][1] = *(const uint32_t*)&sKl[r][kc + 8];
            }
#pragma unroll
            for (int mt = 0; mt < 2; mt++)
#pragma unroll
                for (int nt = 0; nt < 8; nt++) {
                    MMA_BF16(acc[mt][nt], ah[mt], bhf[nt]);
                    MMA_BF16(acc[mt][nt], ah[mt], blf[nt]);
                    MMA_BF16(acc[mt][nt], al[mt], bhf[nt]);
                }
        }
        __syncthreads();
    }

    // Epilogue: exp, bf16 hi/lo split store, partial row sums.
    const float* bp = bias + (size_t)b * LEN;
#pragma unroll
    for (int mt = 0; mt < 2; mt++) {
#pragma unroll
        for (int rr = 0; rr < 2; rr++) {
            int rl = wm * 32 + mt * 16 + g + rr * 8;
            int row = row0 + rl;
            float rs = 0.0f;
#pragma unroll
            for (int nt = 0; nt < 8; nt++) {
                int c = col0 + wn * 64 + nt * 8 + t4 * 2;
                float e0 = __expf(fmaf(acc[mt][nt][rr * 2 + 0], 0.125f, bp[c]));
                float e1 = __expf(fmaf(acc[mt][nt][rr * 2 + 1], 0.125f, bp[c + 1]));
                __nv_bfloat16 h0 = __float2bfloat16(e0);
                __nv_bfloat16 h1 = __float2bfloat16(e1);
                __nv_bfloat16 l0 = __float2bfloat16(e0 - __bfloat162float(h0));
                __nv_bfloat16 l1 = __float2bfloat16(e1 - __bfloat162float(h1));
                size_t off = (size_t)bh * LEN * LEN + (size_t)row * LEN + c;
                __nv_bfloat162 ph; ph.x = h0; ph.y = h1;
                __nv_bfloat162 pl; pl.x = l0; pl.y = l1;
                *(__nv_bfloat162*)(Eh + off) = ph;
                *(__nv_bfloat162*)(El + off) = pl;
                rs += (__bfloat162float(h0) + __bfloat162float(l0))
                    + (__bfloat162float(h1) + __bfloat162float(l1));
            }
            sred[rl][wn * 4 + t4] = rs;
        }
    }
    __syncthreads();
    if (tid < 128) {
        float s = 0.0f;
#pragma unroll
        for (int c = 0; c < 8; c++) s += sred[tid][c];
        psum[((size_t)bh * LEN + row0 + tid) * 16 + blockIdx.x] = s;
    }
}

// ---------------------------------------------------------------------------
__global__ __launch_bounds__(256) void rowsum_kernel(
    const float* __restrict__ psum, float* __restrict__ inv)
{
    size_t idx = (size_t)blockIdx.x * 256 + threadIdx.x;
    float s = 0.0f;
#pragma unroll
    for (int c = 0; c < 16; c++) s += psum[idx * 16 + c];
    inv[idx] = 1.0f / s;
}

// ---------------------------------------------------------------------------
// Normalize + transpose from E planes: align[bh][k][q] = (eh+el)[bh][q][k]*inv
// ---------------------------------------------------------------------------
__global__ void normt_kernel(const __nv_bfloat16* __restrict__ eh,
                             const __nv_bfloat16* __restrict__ el,
                             const float* __restrict__ inv,
                             float* __restrict__ dst)
{
    __shared__ float tile[32][33];
    int bh = blockIdx.z;
    const __nv_bfloat16* sh = eh + (size_t)bh * LEN * LEN;
    const __nv_bfloat16* sl = el + (size_t)bh * LEN * LEN;
    const float* ip = inv + (size_t)bh * LEN;
    float* d = dst + (size_t)bh * LEN * LEN;
    int x = blockIdx.x * 32 + threadIdx.x;
    int y = blockIdx.y * 32 + threadIdx.y;
#pragma unroll
    for (int i = 0; i < 32; i += 8) {
        size_t o = (size_t)(y + i) * LEN + x;
        float e = __bfloat162float(sh[o]) + __bfloat162float(sl[o]);
        tile[threadIdx.y + i][threadIdx.x] = e * ip[y + i];
    }
    __syncthreads();
    int xq = blockIdx.y * 32 + threadIdx.x;
    int yk = blockIdx.x * 32 + threadIdx.y;
#pragma unroll
    for (int i = 0; i < 32; i += 8)
        d[(size_t)(yk + i) * LEN + xq] = tile[threadIdx.x][threadIdx.y + i];
}

// ---------------------------------------------------------------------------
// PV on mma.sync: ctx[q,d] = inv[q] * sum_k E[q][k] * Vt[d][k]
// CTA tile 128(q) x 64(d), BK=32, warps 4(M) x 2(N), warp tile 32x32.
// ---------------------------------------------------------------------------
__global__ __launch_bounds__(256) void wv_mma_kernel(
    const __nv_bfloat16* __restrict__ Eh, const __nv_bfloat16* __restrict__ El,
    const __nv_bfloat16* __restrict__ Vh, const __nv_bfloat16* __restrict__ Vl,
    const float* __restrict__ inv, float* __restrict__ ctx)
{
    __shared__ __nv_bfloat16 sAh[128][40];
    __shared__ __nv_bfloat16 sAl[128][40];
    __shared__ __nv_bfloat16 sBh[64][40];
    __shared__ __nv_bfloat16 sBl[64][40];

    int tid = threadIdx.x;
    int wid = tid >> 5, lid = tid & 31;
    int wm = wid & 3, wn = wid >> 2;
    int g = lid >> 2, t4 = lid & 3;
    int bh = blockIdx.z, b = bh >> 4, h = bh & 15;
    int q0 = blockIdx.y * 128;

    const __nv_bfloat16* Ah = Eh + (size_t)bh * LEN * LEN;
    const __nv_bfloat16* Al = El + (size_t)bh * LEN * LEN;
    const __nv_bfloat16* Bh = Vh + (size_t)bh * DH * LEN;
    const __nv_bfloat16* Bl = Vl + (size_t)bh * DH * LEN;

    float acc[2][4][4];
#pragma unroll
    for (int mt = 0; mt < 2; mt++)
#pragma unroll
        for (int nt = 0; nt < 4; nt++)
#pragma unroll
            for (int i = 0; i < 4; i++) acc[mt][nt][i] = 0.0f;

    for (int kt = 0; kt < LEN; kt += 32) {
#pragma unroll
        for (int e = tid; e < 512; e += 256) {
            int row = e >> 2, cg = (e & 3) * 8;
            size_t ga = (size_t)(q0 + row) * LEN + kt + cg;
            *(uint4*)&sAh[row][cg] = *(const uint4*)(Ah + ga);
            *(uint4*)&sAl[row][cg] = *(const uint4*)(Al + ga);
        }
        {
            int row = tid >> 2, cg = (tid & 3) * 8;
            if (row < 64) {
                size_t gb = (size_t)row * LEN + kt + cg;
                *(uint4*)&sBh[row][cg] = *(const uint4*)(Bh + gb);
                *(uint4*)&sBl[row][cg] = *(const uint4*)(Bl + gb);
            }
        }
        __syncthreads();

#pragma unroll
        for (int ks = 0; ks < 2; ks++) {
            int kc = ks * 16 + t4 * 2;
            uint32_t ah[2][4], al[2][4], bhf[4][2], blf[4][2];
#pragma unroll
            for (int mt = 0; mt < 2; mt++) {
                int r = wm * 32 + mt * 16 + g;
                ah[mt][0] = *(const uint32_t*)&sAh[r][kc];
                ah[mt][1] = *(const uint32_t*)&sAh[r + 8][kc];
                ah[mt][2] = *(const uint32_t*)&sAh[r][kc + 8];
                ah[mt][3] = *(const uint32_t*)&sAh[r + 8][kc + 8];
                al[mt][0] = *(const uint32_t*)&sAl[r][kc];
                al[mt][1] = *(const uint32_t*)&sAl[r + 8][kc];
                al[mt][2] = *(const uint32_t*)&sAl[r][kc + 8];
                al[mt][3] = *(const uint32_t*)&sAl[r + 8][kc + 8];
            }
#pragma unroll
            for (int nt = 0; nt < 4; nt++) {
                int r = wn * 32 + nt * 8 + g;
                bhf[nt][0] = *(const uint32_t*)&sBh[r][kc];
                bhf[nt][1] = *(const uint32_t*)&sBh[r][kc + 8];
                blf[nt][0] = *(const uint32_t*)&sBl[r][kc];
                blf[nt][1] = *(const uint32_t*)&sBl[r][kc + 8];
            }
#pragma unroll
            for (int mt = 0; mt < 2; mt++)
#pragma unroll
                for (int nt = 0; nt < 4; nt++) {
                    MMA_BF16(acc[mt][nt], ah[mt], bhf[nt]);
                    MMA_BF16(acc[mt][nt], ah[mt], blf[nt]);
                    MMA_BF16(acc[mt][nt], al[mt], bhf[nt]);
                }
        }
        __syncthreads();
    }

    // Epilogue: scale by inv[q], store into ctx[b][l][h*64 + d].
#pragma unroll
    for (int mt = 0; mt < 2; mt++) {
        int r = q0 + wm * 32 + mt * 16 + g;
        float s0 = inv[(size_t)bh * LEN + r];
        float s1 = inv[(size_t)bh * LEN + r + 8];
#pragma unroll
        for (int nt = 0; nt < 4; nt++) {
            int c = h * DH + wn * 32 + nt * 8 + t4 * 2;
            *(float2*)(ctx + (size_t)(b * LEN + r) * DIM + c) =
                make_float2(acc[mt][nt][0] * s0, acc[mt][nt][1] * s0);
            *(float2*)(ctx + (size_t)(b * LEN + r + 8) * DIM + c) =
                make_float2(acc[mt][nt][2] * s1, acc[mt][nt][3] * s1);
        }
    }
}

// ---------------------------------------------------------------------------
extern "C" void kernel_launch(void* const* d_in, const int* in_sizes, int n_in,
                              void* d_out, int out_size)
{
    const float* queries = (const float*)d_in[0];
    const float* bias    = (const float*)d_in[1];
    const float* w_qkv   = (const float*)d_in[2];
    const float* w_o     = (const float*)d_in[3];
    float* out = (float*)d_out;
    float* align = out + (size_t)BSZ * LEN * DIM;

    float *qkv, *ctx, *psum, *inv;
    __nv_bfloat16 *ah, *al, *bh, *bl, *kh, *kl, *eh, *el, *vth, *vtl;
    cudaGetSymbolAddress((void**)&qkv,  g_qkv);
    cudaGetSymbolAddress((void**)&ctx,  g_ctx);
    cudaGetSymbolAddress((void**)&psum, g_psum);
    cudaGetSymbolAddress((void**)&inv,  g_inv);
    cudaGetSymbolAddress((void**)&ah,  g_ah);
    cudaGetSymbolAddress((void**)&al,  g_al);
    cudaGetSymbolAddress((void**)&bh,  g_bh);
    cudaGetSymbolAddress((void**)&bl,  g_bl);
    cudaGetSymbolAddress((void**)&kh,  g_kh);
    cudaGetSymbolAddress((void**)&kl,  g_kl);
    cudaGetSymbolAddress((void**)&eh,  g_eh);
    cudaGetSymbolAddress((void**)&el,  g_el);
    cudaGetSymbolAddress((void**)&vth, g_vth);
    cudaGetSymbolAddress((void**)&vtl, g_vtl);

    const int MROWS = BSZ * LEN;  // 4096

    // 1) QKV projection on tensor cores
    split_rm_kernel<<<(MROWS * DIM) / 256, 256>>>(queries, ah, al, MROWS * DIM);
    split_tr_kernel<<<dim3(D3 / 32, DIM / 32), dim3(32, 8)>>>(w_qkv, bh, bl, DIM, D3);
    mma_gemm_kernel<<<dim3(D3 / 128, MROWS / 128), 256>>>(ah, al, bh, bl, qkv, D3, DIM);

    // 2) Prep attention operands: Q/K planes (reuse ah/al for Q), V transposed planes
    qksplit_kernel<<<(MROWS * 2048) / 256, 256>>>(qkv, ah, al, kh, kl);
    vtsplit_kernel<<<dim3(LEN / 32, DH / 32, BSZ * NH), dim3(32, 8)>>>(qkv, vth, vtl);

    // 3) e = exp(scale*QK^T + bias) on tensor cores -> E planes + partial sums
    qk_mma_kernel<<<dim3(LEN / 128, LEN / 128, BSZ * NH), 256>>>(
        ah, al, kh, kl, bias, eh, el, psum);

    // 4) row sums -> reciprocals
    rowsum_kernel<<<(BSZ * NH * LEN) / 256, 256>>>(psum, inv);

    // 5) align = normalized transposed weights (from E planes)
    normt_kernel<<<dim3(LEN / 32, LEN / 32, BSZ * NH), dim3(32, 8)>>>(eh, el, inv, align);

    // 6) ctx = inv * (E @ V) on tensor cores
    wv_mma_kernel<<<dim3(1, LEN / 128, BSZ * NH), 256>>>(eh, el, vth, vtl, inv, ctx);

    // 7) out = ctx @ w_o on tensor cores
    split_rm_kernel<<<(MROWS * DIM) / 256, 256>>>(ctx, ah, al, MROWS * DIM);
    split_tr_kernel<<<dim3(DIM / 32, DIM / 32), dim3(32, 8)>>>(w_o, bh, bl, DIM, DIM);
    mma_gemm_kernel<<<dim3(DIM / 128, MROWS / 128), 256>>>(ah, al, bh, bl, out, DIM, DIM);
}